// round 1
// baseline (speedup 1.0000x reference)
#include <cuda_runtime.h>
#include <cstdint>

// Problem constants
#define BB   2
#define QQ   1024
#define MM   1024
#define UU   1024
#define HH   16
#define DHH  64
#define KL   2048   // MEM + Q

// ---------------------------------------------------------------------------
// Scratch (allocation-free: __device__ globals)
// ---------------------------------------------------------------------------
__device__ float g_full[(size_t)BB * KL * UU];           // 16 MB
__device__ float g_wq  [(size_t)BB * QQ * UU];           // 8 MB
__device__ float g_qc  [(size_t)BB * QQ * UU];           // 8 MB
__device__ float g_qr  [(size_t)BB * QQ * UU];           // 8 MB
__device__ float g_wkv [(size_t)BB * KL * 2 * UU];       // 32 MB
__device__ float g_wr  [(size_t)BB * KL * UU];           // 16 MB
__device__ float g_sc  [(size_t)BB * HH * QQ * KL];      // 256 MB (scores ctx, then P)
__device__ float g_sr  [(size_t)BB * HH * QQ * KL];      // 256 MB (relative scores, unshifted)
__device__ float g_ctx [(size_t)BB * QQ * UU];           // 8 MB

// ---------------------------------------------------------------------------
// concat(memories, inputs) -> g_full   [B, KLEN, U]
// ---------------------------------------------------------------------------
__global__ void concat_kernel(const float* __restrict__ mem,
                              const float* __restrict__ inp) {
    size_t i = (size_t)blockIdx.x * blockDim.x + threadIdx.x;   // float4 index
    const size_t total4 = (size_t)BB * KL * UU / 4;
    if (i >= total4) return;
    size_t elem = i * 4;
    int b = (int)(elem / ((size_t)KL * UU));
    size_t rem = elem % ((size_t)KL * UU);
    int t = (int)(rem / UU);
    int u = (int)(rem % UU);
    float4 v;
    if (t < MM) {
        v = *(const float4*)(mem + ((size_t)b * MM + t) * UU + u);
    } else {
        v = *(const float4*)(inp + ((size_t)b * QQ + (t - MM)) * UU + u);
    }
    ((float4*)g_full)[i] = v;
}

// ---------------------------------------------------------------------------
// qc = wq + bias_context ; qr = wq + bias_relative
// ---------------------------------------------------------------------------
__global__ void biasadd_kernel(const float* __restrict__ bc,
                               const float* __restrict__ br) {
    size_t i = (size_t)blockIdx.x * blockDim.x + threadIdx.x;   // float4 index
    const size_t total4 = (size_t)BB * QQ * UU / 4;
    if (i >= total4) return;
    int u4 = (int)(i % (UU / 4));
    float4 w = ((const float4*)g_wq)[i];
    float4 c = ((const float4*)bc)[u4];
    float4 r = ((const float4*)br)[u4];
    float4 oc = make_float4(w.x + c.x, w.y + c.y, w.z + c.z, w.w + c.w);
    float4 orr = make_float4(w.x + r.x, w.y + r.y, w.z + r.z, w.w + r.w);
    ((float4*)g_qc)[i] = oc;
    ((float4*)g_qr)[i] = orr;
}

// ---------------------------------------------------------------------------
// SGEMM 128x128x8, 256 threads, 8x8 microtile.
// NT = false : C[m,n] = sum_k A[m,k] * B[k,n]   (B row-major [K,N], ldb)
// NT = true  : C[m,n] = sum_k A[m,k] * B[n,k]   (B row-major [N,K], ldb)
// Batched over gridDim.z with z = z1*innerB + z2; per-operand offsets
// off = z1*s1 + z2*s2 (lets us batch over (b, h) with different strides).
// Requires K % 8 == 0, N % 4 == 0, 16B-aligned base pointers / lds.
// ---------------------------------------------------------------------------
template <bool NT>
__global__ void __launch_bounds__(256)
sgemm_kernel(const float* __restrict__ A, int lda, long long sA1, long long sA2,
             const float* __restrict__ B, int ldb, long long sB1, long long sB2,
             float* __restrict__ C, int ldc, long long sC1, long long sC2,
             int M, int N, int K, int innerB) {
    int z  = blockIdx.z;
    int z1 = z / innerB, z2 = z % innerB;
    A += (size_t)z1 * sA1 + (size_t)z2 * sA2;
    B += (size_t)z1 * sB1 + (size_t)z2 * sB2;
    C += (size_t)z1 * sC1 + (size_t)z2 * sC2;

    __shared__ float As[8][128];
    __shared__ float Bs[8][128];

    const int bm = blockIdx.y * 128;
    const int bn = blockIdx.x * 128;
    const int tid = threadIdx.x;
    const int tx = tid & 15;        // 0..15 -> column groups
    const int ty = tid >> 4;        // 0..15 -> row groups

    // A tile loading map: 128 rows x 8 cols, each thread one float4
    const int arow = tid >> 1;            // 0..127
    const int acol = (tid & 1) * 4;       // 0 or 4
    // B tile loading map (NN): 8 rows x 128 cols
    const int brow = tid >> 5;            // 0..7
    const int bcol = (tid & 31) * 4;      // 0..124
    // B tile loading map (NT): 128 rows (n) x 8 cols (k)
    const int ntrow = tid >> 1;           // 0..127
    const int ntcol = (tid & 1) * 4;      // 0 or 4

    float acc[8][8];
#pragma unroll
    for (int i = 0; i < 8; i++)
#pragma unroll
        for (int j = 0; j < 8; j++) acc[i][j] = 0.0f;

    for (int k0 = 0; k0 < K; k0 += 8) {
        // ---- load A tile ----
        float4 av = make_float4(0.f, 0.f, 0.f, 0.f);
        int gar = bm + arow;
        if (gar < M)
            av = *(const float4*)(A + (size_t)gar * lda + k0 + acol);
        As[acol + 0][arow] = av.x;
        As[acol + 1][arow] = av.y;
        As[acol + 2][arow] = av.z;
        As[acol + 3][arow] = av.w;

        // ---- load B tile ----
        if (!NT) {
            float4 bv = make_float4(0.f, 0.f, 0.f, 0.f);
            if (bn + bcol < N)
                bv = *(const float4*)(B + (size_t)(k0 + brow) * ldb + bn + bcol);
            Bs[brow][bcol + 0] = bv.x;
            Bs[brow][bcol + 1] = bv.y;
            Bs[brow][bcol + 2] = bv.z;
            Bs[brow][bcol + 3] = bv.w;
        } else {
            float4 bv = make_float4(0.f, 0.f, 0.f, 0.f);
            int gbr = bn + ntrow;
            if (gbr < N)
                bv = *(const float4*)(B + (size_t)gbr * ldb + k0 + ntcol);
            Bs[ntcol + 0][ntrow] = bv.x;
            Bs[ntcol + 1][ntrow] = bv.y;
            Bs[ntcol + 2][ntrow] = bv.z;
            Bs[ntcol + 3][ntrow] = bv.w;
        }
        __syncthreads();

        // ---- compute ----
#pragma unroll
        for (int kk = 0; kk < 8; kk++) {
            float af[8], bf[8];
#pragma unroll
            for (int i = 0; i < 8; i++) af[i] = As[kk][ty * 8 + i];
            // split B fragment: cols tx*4..tx*4+3 and 64+tx*4..64+tx*4+3
#pragma unroll
            for (int j = 0; j < 4; j++) bf[j] = Bs[kk][tx * 4 + j];
#pragma unroll
            for (int j = 0; j < 4; j++) bf[4 + j] = Bs[kk][64 + tx * 4 + j];
#pragma unroll
            for (int i = 0; i < 8; i++)
#pragma unroll
                for (int j = 0; j < 8; j++)
                    acc[i][j] = fmaf(af[i], bf[j], acc[i][j]);
        }
        __syncthreads();
    }

    // ---- store ----
#pragma unroll
    for (int i = 0; i < 8; i++) {
        int row = bm + ty * 8 + i;
        if (row >= M) continue;
#pragma unroll
        for (int j = 0; j < 8; j++) {
            int col = bn + ((j < 4) ? (tx * 4 + j) : (64 + tx * 4 + (j - 4)));
            if (col < N)
                C[(size_t)row * ldc + col] = acc[i][j];
        }
    }
}

// ---------------------------------------------------------------------------
// Masked softmax with relative shift.
// P[q,k] = softmax_k( (Sc[q,k] + Sr[q, k + Q-1-q]) / 8 ),  k <= MEM + q
// Written in place into g_sc; masked tail zero-filled.
// ---------------------------------------------------------------------------
__global__ void softmax_kernel() {
    const int q = blockIdx.x;
    const int h = blockIdx.y;
    const int b = blockIdx.z;
    const int cnt = MM + q + 1;           // valid keys
    const int tid = threadIdx.x;          // 256 threads

    float* rowc = g_sc + (((size_t)b * HH + h) * QQ + q) * KL;
    const float* rowr = g_sr + (((size_t)b * HH + h) * QQ + q) * KL + (QQ - 1 - q);

    __shared__ float red[256];

    // pass 1: combine + scale + max
    float mx = -1e30f;
    for (int k = tid; k < cnt; k += 256) {
        float v = (rowc[k] + rowr[k]) * 0.125f;
        rowc[k] = v;
        mx = fmaxf(mx, v);
    }
    red[tid] = mx;
    __syncthreads();
    for (int s = 128; s > 0; s >>= 1) {
        if (tid < s) red[tid] = fmaxf(red[tid], red[tid + s]);
        __syncthreads();
    }
    mx = red[0];
    __syncthreads();

    // pass 2: exp + sum
    float sum = 0.f;
    for (int k = tid; k < cnt; k += 256) {
        float e = expf(rowc[k] - mx);
        rowc[k] = e;
        sum += e;
    }
    red[tid] = sum;
    __syncthreads();
    for (int s = 128; s > 0; s >>= 1) {
        if (tid < s) red[tid] += red[tid + s];
        __syncthreads();
    }
    float inv = 1.0f / red[0];

    // pass 3: normalize + zero masked tail
    for (int k = tid; k < cnt; k += 256) rowc[k] *= inv;
    for (int k = cnt + tid; k < KL; k += 256) rowc[k] = 0.f;
}

// ---------------------------------------------------------------------------
// Launch
// ---------------------------------------------------------------------------
extern "C" void kernel_launch(void* const* d_in, const int* in_sizes, int n_in,
                              void* d_out, int out_size) {
    const float* inputs    = (const float*)d_in[0];
    const float* relatives = (const float*)d_in[1];
    const float* memories  = (const float*)d_in[2];
    const float* bias_c    = (const float*)d_in[3];
    const float* bias_r    = (const float*)d_in[4];
    const float* Wq        = (const float*)d_in[5];
    const float* Wkv       = (const float*)d_in[6];
    const float* Wr        = (const float*)d_in[7];
    const float* Wo        = (const float*)d_in[8];
    float* out             = (float*)d_out;

    float *p_full, *p_wq, *p_qc, *p_qr, *p_wkv, *p_wr, *p_sc, *p_sr, *p_ctx;
    cudaGetSymbolAddress((void**)&p_full, g_full);
    cudaGetSymbolAddress((void**)&p_wq,  g_wq);
    cudaGetSymbolAddress((void**)&p_qc,  g_qc);
    cudaGetSymbolAddress((void**)&p_qr,  g_qr);
    cudaGetSymbolAddress((void**)&p_wkv, g_wkv);
    cudaGetSymbolAddress((void**)&p_wr,  g_wr);
    cudaGetSymbolAddress((void**)&p_sc,  g_sc);
    cudaGetSymbolAddress((void**)&p_sr,  g_sr);
    cudaGetSymbolAddress((void**)&p_ctx, g_ctx);

    dim3 blk(256);

    // 1. w_q = inputs @ Wq    [2048,1024] = [2048,1024]x[1024,1024]
    sgemm_kernel<false><<<dim3(UU / 128, (BB * QQ) / 128, 1), blk>>>(
        inputs, UU, 0, 0, Wq, UU, 0, 0, p_wq, UU, 0, 0,
        BB * QQ, UU, UU, 1);

    // 2. full = concat(mem, inp)
    {
        size_t total4 = (size_t)BB * KL * UU / 4;
        concat_kernel<<<(unsigned)((total4 + 255) / 256), 256>>>(memories, inputs);
    }

    // 3. w_kv = full @ Wkv    [4096,2048]
    sgemm_kernel<false><<<dim3((2 * UU) / 128, (BB * KL) / 128, 1), blk>>>(
        p_full, UU, 0, 0, Wkv, 2 * UU, 0, 0, p_wkv, 2 * UU, 0, 0,
        BB * KL, 2 * UU, UU, 1);

    // 4. w_r = relatives @ Wr [4096,1024]
    sgemm_kernel<false><<<dim3(UU / 128, (BB * KL) / 128, 1), blk>>>(
        relatives, UU, 0, 0, Wr, UU, 0, 0, p_wr, UU, 0, 0,
        BB * KL, UU, UU, 1);

    // 5. qc, qr = wq + biases
    {
        size_t total4 = (size_t)BB * QQ * UU / 4;
        biasadd_kernel<<<(unsigned)((total4 + 255) / 256), 256>>>(bias_c, bias_r);
    }

    // 6. Sc[b,h] = qc(b,h) [Q,64] @ K(b,h)[KL,64]^T   (batched NT, z = b*H+h)
    sgemm_kernel<true><<<dim3(KL / 128, QQ / 128, BB * HH), blk>>>(
        p_qc, UU, (long long)QQ * UU, 64,
        p_wkv, 2 * UU, (long long)KL * 2 * UU, 64,
        p_sc, KL, (long long)HH * QQ * KL, (long long)QQ * KL,
        QQ, KL, DHH, HH);

    // 7. Sr[b,h] = qr(b,h) @ R(b,h)^T
    sgemm_kernel<true><<<dim3(KL / 128, QQ / 128, BB * HH), blk>>>(
        p_qr, UU, (long long)QQ * UU, 64,
        p_wr, UU, (long long)KL * UU, 64,
        p_sr, KL, (long long)HH * QQ * KL, (long long)QQ * KL,
        QQ, KL, DHH, HH);

    // 8. masked softmax with relative shift -> P in g_sc
    softmax_kernel<<<dim3(QQ, HH, BB), 256>>>();

    // 9. ctx(b,h) = P(b,h) [Q,KL] @ V(b,h) [KL,64]   (batched NN)
    sgemm_kernel<false><<<dim3(1, QQ / 128, BB * HH), blk>>>(
        p_sc, KL, (long long)HH * QQ * KL, (long long)QQ * KL,
        p_wkv + UU, 2 * UU, (long long)KL * 2 * UU, 64,
        p_ctx, UU, (long long)QQ * UU, 64,
        QQ, DHH, KL, HH);

    // 10. out = ctx @ Wo
    sgemm_kernel<false><<<dim3(UU / 128, (BB * QQ) / 128, 1), blk>>>(
        p_ctx, UU, 0, 0, Wo, UU, 0, 0, out, UU, 0, 0,
        BB * QQ, UU, UU, 1);
}

// round 3
// speedup vs baseline: 3.1595x; 3.1595x over previous
#include <cuda_runtime.h>
#include <cstdint>

// Problem constants
#define BB   2
#define QQ   1024
#define MEMN 1024
#define UU   1024
#define HH   16
#define DHH  64
#define KL   2048   // MEM + Q

// ---------------------------------------------------------------------------
// Scratch (allocation-free: __device__ globals)
// ---------------------------------------------------------------------------
__device__ float g_full[(size_t)BB * KL * UU];           // 16 MB (tf32-rounded)
__device__ float g_relr[(size_t)BB * KL * UU];           // 16 MB rounded relatives
__device__ float g_wq  [(size_t)BB * QQ * UU];           // 8 MB
__device__ float g_qc  [(size_t)BB * QQ * UU];           // 8 MB (rounded)
__device__ float g_qr  [(size_t)BB * QQ * UU];           // 8 MB (rounded)
__device__ float g_wkv [(size_t)BB * KL * 2 * UU];       // 32 MB (rounded)
__device__ float g_wr  [(size_t)BB * KL * UU];           // 16 MB (rounded)
__device__ float g_sc  [(size_t)BB * HH * QQ * KL];      // 256 MB (Sc, then P rounded)
__device__ float g_sr  [(size_t)BB * HH * QQ * KL];      // 256 MB (Sr unshifted)
__device__ float g_ctx [(size_t)BB * QQ * UU];           // 8 MB (rounded)
__device__ float g_wqT [(size_t)UU * UU];                // 4 MB (rounded)
__device__ float g_wkvT[(size_t)2 * UU * UU];            // 8 MB (rounded)
__device__ float g_wrT [(size_t)UU * UU];                // 4 MB (rounded)
__device__ float g_woT [(size_t)UU * UU];                // 4 MB (rounded)
__device__ float g_vt  [(size_t)BB * HH * DHH * KL];     // 16 MB [b,h,d,t] (rounded)

// ---------------------------------------------------------------------------
// Helpers
// ---------------------------------------------------------------------------
__device__ __forceinline__ uint32_t smem_to_u32(const void* p) {
    uint32_t a;
    asm("{ .reg .u64 t; cvta.to.shared.u64 t, %1; cvt.u32.u64 %0, t; }" : "=r"(a) : "l"(p));
    return a;
}
// Round fp32 -> tf32 (round-to-nearest): kills the coherent truncation bias
__device__ __forceinline__ float tf32r(float x) {
    float y;
    asm("cvt.rna.tf32.f32 %0, %1;" : "=f"(y) : "f"(x));
    return y;
}
__device__ __forceinline__ void cp_async16(uint32_t saddr, const void* gaddr) {
    asm volatile("cp.async.cg.shared.global [%0], [%1], 16;" :: "r"(saddr), "l"(gaddr));
}
#define CP_COMMIT() asm volatile("cp.async.commit_group;" ::: "memory")
#define CP_WAIT1()  asm volatile("cp.async.wait_group 1;" ::: "memory")

__device__ __forceinline__ void mma_tf32(float acc[4], const uint32_t a[4], const uint32_t b[2]) {
    asm volatile("mma.sync.aligned.m16n8k8.row.col.f32.tf32.tf32.f32 "
        "{%0,%1,%2,%3}, {%4,%5,%6,%7}, {%8,%9}, {%0,%1,%2,%3};"
        : "+f"(acc[0]), "+f"(acc[1]), "+f"(acc[2]), "+f"(acc[3])
        : "r"(a[0]), "r"(a[1]), "r"(a[2]), "r"(a[3]), "r"(b[0]), "r"(b[1]));
}

// ---------------------------------------------------------------------------
// concat(memories, inputs) -> g_full (tf32-rounded)   [B, KLEN, U]
// ---------------------------------------------------------------------------
__global__ void concat_kernel(const float* __restrict__ mem,
                              const float* __restrict__ inp) {
    size_t i = (size_t)blockIdx.x * blockDim.x + threadIdx.x;
    const size_t total4 = (size_t)BB * KL * UU / 4;
    if (i >= total4) return;
    size_t elem = i * 4;
    int b = (int)(elem / ((size_t)KL * UU));
    size_t rem = elem % ((size_t)KL * UU);
    int t = (int)(rem / UU);
    int u = (int)(rem % UU);
    float4 v;
    if (t < MEMN) v = *(const float4*)(mem + ((size_t)b * MEMN + t) * UU + u);
    else          v = *(const float4*)(inp + ((size_t)b * QQ + (t - MEMN)) * UU + u);
    v.x = tf32r(v.x); v.y = tf32r(v.y); v.z = tf32r(v.z); v.w = tf32r(v.w);
    ((float4*)g_full)[i] = v;
}

// ---------------------------------------------------------------------------
// rounded copy: out = tf32(in)
// ---------------------------------------------------------------------------
__global__ void roundcopy_kernel(const float* __restrict__ in, float* __restrict__ out,
                                 size_t total4) {
    size_t i = (size_t)blockIdx.x * blockDim.x + threadIdx.x;
    if (i >= total4) return;
    float4 v = ((const float4*)in)[i];
    v.x = tf32r(v.x); v.y = tf32r(v.y); v.z = tf32r(v.z); v.w = tf32r(v.w);
    ((float4*)out)[i] = v;
}

// ---------------------------------------------------------------------------
// qc = tf32(wq + bias_context) ; qr = tf32(wq + bias_relative)
// ---------------------------------------------------------------------------
__global__ void biasadd_kernel(const float* __restrict__ bc,
                               const float* __restrict__ br) {
    size_t i = (size_t)blockIdx.x * blockDim.x + threadIdx.x;
    const size_t total4 = (size_t)BB * QQ * UU / 4;
    if (i >= total4) return;
    int u4 = (int)(i % (UU / 4));
    float4 w = ((const float4*)g_wq)[i];
    float4 c = ((const float4*)bc)[u4];
    float4 r = ((const float4*)br)[u4];
    float4 oc = make_float4(tf32r(w.x + c.x), tf32r(w.y + c.y), tf32r(w.z + c.z), tf32r(w.w + c.w));
    float4 orr = make_float4(tf32r(w.x + r.x), tf32r(w.y + r.y), tf32r(w.z + r.z), tf32r(w.w + r.w));
    ((float4*)g_qc)[i] = oc;
    ((float4*)g_qr)[i] = orr;
}

// ---------------------------------------------------------------------------
// Batched strided transpose with tf32 rounding: out[c, r] = tf32(in[r, c])
// ---------------------------------------------------------------------------
__global__ void transpose_kernel(const float* __restrict__ in, float* __restrict__ out,
                                 int ld_in, int ld_out,
                                 long long sIn1, long long sIn2,
                                 long long sOut1, long long sOut2, int innerB) {
    __shared__ float t[32][33];
    int z = blockIdx.z, z1 = z / innerB, z2 = z % innerB;
    in  += (size_t)z1 * sIn1  + (size_t)z2 * sIn2;
    out += (size_t)z1 * sOut1 + (size_t)z2 * sOut2;
    int r0 = blockIdx.y * 32, c0 = blockIdx.x * 32;
    int tx = threadIdx.x, ty = threadIdx.y;
#pragma unroll
    for (int i = 0; i < 32; i += 8)
        t[ty + i][tx] = in[(size_t)(r0 + ty + i) * ld_in + c0 + tx];
    __syncthreads();
#pragma unroll
    for (int i = 0; i < 32; i += 8)
        out[(size_t)(c0 + ty + i) * ld_out + r0 + tx] = tf32r(t[tx][ty + i]);
}

// ---------------------------------------------------------------------------
// tf32 mma.sync GEMM:  C[m,n] = sum_k A[m,k] * B[n,k]
//   A row-major [M,K] (lda), B row-major [N,K] (ldb); inputs pre-rounded tf32.
//   CTA tile BM x BN, K-chunk 16, 3-stage cp.async pipeline, 8 warps.
//   Warp tile WM x WN via m16n8k8 fragments. Batched over blockIdx.z.
// ---------------------------------------------------------------------------
template <int BM, int BN, int WM, int WN, bool ROUND_OUT>
__global__ void __launch_bounds__(256)
mma_gemm(const float* __restrict__ A, int lda, long long sA1, long long sA2,
         const float* __restrict__ B, int ldb, long long sB1, long long sB2,
         float* __restrict__ C, int ldc, long long sC1, long long sC2,
         int K, int innerB) {
    constexpr int KC = 16;
    constexpr int LDSS = 20;   // padded SMEM row stride (floats), conflict-free
    constexpr int WARPS_M = BM / WM;
    constexpr int WARPS_N = BN / WN;
    constexpr int MFRAG = WM / 16;
    constexpr int NFRAG = WN / 8;
    static_assert(WARPS_M * WARPS_N * 32 == 256, "warp layout");

    extern __shared__ float sm[];
    float* As = sm;                       // [3][BM][LDSS]
    float* Bs = sm + 3 * BM * LDSS;       // [3][BN][LDSS]
    const uint32_t sA_base = smem_to_u32(As);
    const uint32_t sB_base = smem_to_u32(Bs);

    const int tid = threadIdx.x;
    const int lane = tid & 31;
    const int warp = tid >> 5;
    const int wm = warp % WARPS_M;
    const int wn = warp / WARPS_M;

    const int z = blockIdx.z;
    const int z1 = z / innerB, z2 = z % innerB;
    A += (size_t)z1 * sA1 + (size_t)z2 * sA2;
    B += (size_t)z1 * sB1 + (size_t)z2 * sB2;
    C += (size_t)z1 * sC1 + (size_t)z2 * sC2;
    const int bm = blockIdx.y * BM;
    const int bn = blockIdx.x * BN;
    const float* Ag = A + (size_t)bm * lda;
    const float* Bg = B + (size_t)bn * ldb;

    const int nIter = K / KC;

    auto load_stage = [&](int stage, int buf) {
#pragma unroll
        for (int i = 0; i < (BM * 4) / 256; i++) {
            int idx = tid + i * 256;
            int row = idx >> 2, ch = idx & 3;
            uint32_t s = sA_base + (uint32_t)(buf * BM * LDSS + row * LDSS + ch * 4) * 4u;
            cp_async16(s, Ag + (size_t)row * lda + stage * KC + ch * 4);
        }
#pragma unroll
        for (int i = 0; i < (BN * 4) / 256; i++) {
            int idx = tid + i * 256;
            int row = idx >> 2, ch = idx & 3;
            uint32_t s = sB_base + (uint32_t)(buf * BN * LDSS + row * LDSS + ch * 4) * 4u;
            cp_async16(s, Bg + (size_t)row * ldb + stage * KC + ch * 4);
        }
    };

    float acc[MFRAG][NFRAG][4];
#pragma unroll
    for (int i = 0; i < MFRAG; i++)
#pragma unroll
        for (int j = 0; j < NFRAG; j++)
#pragma unroll
            for (int v = 0; v < 4; v++) acc[i][j][v] = 0.0f;

    // prologue: stages 0, 1
    load_stage(0, 0); CP_COMMIT();
    if (nIter > 1) load_stage(1, 1);
    CP_COMMIT();

    const int r4 = lane >> 2;   // 0..7
    const int c4 = lane & 3;    // 0..3

    for (int it = 0; it < nIter; ++it) {
        CP_WAIT1();
        __syncthreads();
        if (it + 2 < nIter) load_stage(it + 2, (it + 2) % 3);
        CP_COMMIT();

        const float* a_ = As + (it % 3) * BM * LDSS + (wm * WM) * LDSS;
        const float* b_ = Bs + (it % 3) * BN * LDSS + (wn * WN) * LDSS;

#pragma unroll
        for (int k8 = 0; k8 < KC; k8 += 8) {
            uint32_t af[MFRAG][4];
            uint32_t bf[NFRAG][2];
#pragma unroll
            for (int fm = 0; fm < MFRAG; fm++) {
                const float* ap = a_ + (fm * 16 + r4) * LDSS + k8 + c4;
                af[fm][0] = __float_as_uint(ap[0]);
                af[fm][1] = __float_as_uint(ap[8 * LDSS]);
                af[fm][2] = __float_as_uint(ap[4]);
                af[fm][3] = __float_as_uint(ap[8 * LDSS + 4]);
            }
#pragma unroll
            for (int fn = 0; fn < NFRAG; fn++) {
                const float* bp = b_ + (fn * 8 + r4) * LDSS + k8 + c4;
                bf[fn][0] = __float_as_uint(bp[0]);
                bf[fn][1] = __float_as_uint(bp[4]);
            }
#pragma unroll
            for (int fm = 0; fm < MFRAG; fm++)
#pragma unroll
                for (int fn = 0; fn < NFRAG; fn++)
                    mma_tf32(acc[fm][fn], af[fm], bf[fn]);
        }
    }

    // epilogue
    const int m0 = bm + wm * WM;
    const int n0 = bn + wn * WN;
#pragma unroll
    for (int fm = 0; fm < MFRAG; fm++) {
#pragma unroll
        for (int fn = 0; fn < NFRAG; fn++) {
            int r = m0 + fm * 16 + r4;
            int cidx = n0 + fn * 8 + c4 * 2;
            float2 v0 = make_float2(acc[fm][fn][0], acc[fm][fn][1]);
            float2 v1 = make_float2(acc[fm][fn][2], acc[fm][fn][3]);
            if (ROUND_OUT) {
                v0.x = tf32r(v0.x); v0.y = tf32r(v0.y);
                v1.x = tf32r(v1.x); v1.y = tf32r(v1.y);
            }
            *(float2*)(C + (size_t)r * ldc + cidx) = v0;
            *(float2*)(C + (size_t)(r + 8) * ldc + cidx) = v1;
        }
    }
}

// ---------------------------------------------------------------------------
// Masked softmax with relative shift (single pass, register-resident).
// P[q,k] = softmax_k( (Sc[q,k] + Sr[q, k + Q-1-q]) / 8 ),  k <= MEM + q
// Output tf32-rounded (consumed by P @ V^T mma GEMM).
// ---------------------------------------------------------------------------
__global__ void __launch_bounds__(256) softmax_kernel() {
    const int q = blockIdx.x, h = blockIdx.y, b = blockIdx.z;
    const int cnt = MEMN + q + 1;
    const int tid = threadIdx.x;

    float* rowc = g_sc + (((size_t)b * HH + h) * QQ + q) * KL;
    const float* rowr = g_sr + (((size_t)b * HH + h) * QQ + q) * KL + (QQ - 1 - q);

    float v[8];
    float mx = -1e30f;
#pragma unroll
    for (int i = 0; i < 8; i++) {
        int k = tid + i * 256;
        if (k < cnt) {
            v[i] = (rowc[k] + rowr[k]) * 0.125f;
            mx = fmaxf(mx, v[i]);
        } else v[i] = -1e30f;
    }
    __shared__ float red[8];
#pragma unroll
    for (int o = 16; o; o >>= 1) mx = fmaxf(mx, __shfl_xor_sync(~0u, mx, o));
    if ((tid & 31) == 0) red[tid >> 5] = mx;
    __syncthreads();
    if (tid == 0) {
        float m = red[0];
#pragma unroll
        for (int i = 1; i < 8; i++) m = fmaxf(m, red[i]);
        red[0] = m;
    }
    __syncthreads();
    mx = red[0];

    float sum = 0.f;
#pragma unroll
    for (int i = 0; i < 8; i++) {
        float e = __expf(v[i] - mx);
        v[i] = e;
        sum += e;
    }
    __syncthreads();
#pragma unroll
    for (int o = 16; o; o >>= 1) sum += __shfl_xor_sync(~0u, sum, o);
    if ((tid & 31) == 0) red[tid >> 5] = sum;
    __syncthreads();
    if (tid == 0) {
        float s = 0.f;
#pragma unroll
        for (int i = 0; i < 8; i++) s += red[i];
        red[0] = s;
    }
    __syncthreads();
    const float inv = 1.0f / red[0];

#pragma unroll
    for (int i = 0; i < 8; i++) {
        int k = tid + i * 256;
        rowc[k] = (k < cnt) ? tf32r(v[i] * inv) : 0.f;
    }
}

// ---------------------------------------------------------------------------
// Launch
// ---------------------------------------------------------------------------
extern "C" void kernel_launch(void* const* d_in, const int* in_sizes, int n_in,
                              void* d_out, int out_size) {
    const float* inputs    = (const float*)d_in[0];
    const float* relatives = (const float*)d_in[1];
    const float* memories  = (const float*)d_in[2];
    const float* bias_c    = (const float*)d_in[3];
    const float* bias_r    = (const float*)d_in[4];
    const float* Wq        = (const float*)d_in[5];
    const float* Wkv       = (const float*)d_in[6];
    const float* Wr        = (const float*)d_in[7];
    const float* Wo        = (const float*)d_in[8];
    float* out             = (float*)d_out;

    float *p_full, *p_relr, *p_wq, *p_qc, *p_qr, *p_wkv, *p_wr, *p_sc, *p_sr, *p_ctx;
    float *p_wqT, *p_wkvT, *p_wrT, *p_woT, *p_vt;
    cudaGetSymbolAddress((void**)&p_full, g_full);
    cudaGetSymbolAddress((void**)&p_relr, g_relr);
    cudaGetSymbolAddress((void**)&p_wq,   g_wq);
    cudaGetSymbolAddress((void**)&p_qc,   g_qc);
    cudaGetSymbolAddress((void**)&p_qr,   g_qr);
    cudaGetSymbolAddress((void**)&p_wkv,  g_wkv);
    cudaGetSymbolAddress((void**)&p_wr,   g_wr);
    cudaGetSymbolAddress((void**)&p_sc,   g_sc);
    cudaGetSymbolAddress((void**)&p_sr,   g_sr);
    cudaGetSymbolAddress((void**)&p_ctx,  g_ctx);
    cudaGetSymbolAddress((void**)&p_wqT,  g_wqT);
    cudaGetSymbolAddress((void**)&p_wkvT, g_wkvT);
    cudaGetSymbolAddress((void**)&p_wrT,  g_wrT);
    cudaGetSymbolAddress((void**)&p_woT,  g_woT);
    cudaGetSymbolAddress((void**)&p_vt,   g_vt);

    // dynamic smem: 3 stages * (BM + BN) rows * 20 floats * 4 B
    constexpr int SMEM_A = 3 * (128 + 128) * 20 * 4;   // 61440
    constexpr int SMEM_B = 3 * (128 + 64) * 20 * 4;    // 46080
    cudaFuncSetAttribute((const void*)mma_gemm<128,128,64,32,false>,
                         cudaFuncAttributeMaxDynamicSharedMemorySize, SMEM_A);
    cudaFuncSetAttribute((const void*)mma_gemm<128,128,64,32,true>,
                         cudaFuncAttributeMaxDynamicSharedMemorySize, SMEM_A);
    cudaFuncSetAttribute((const void*)mma_gemm<128,64,32,32,true>,
                         cudaFuncAttributeMaxDynamicSharedMemorySize, SMEM_B);

    dim3 tblk(32, 8);

    // 0. rounded transposed weights -> [N, K] K-major
    transpose_kernel<<<dim3(UU / 32, UU / 32, 1), tblk>>>(Wq, p_wqT, UU, UU, 0, 0, 0, 0, 1);
    transpose_kernel<<<dim3((2 * UU) / 32, UU / 32, 1), tblk>>>(Wkv, p_wkvT, 2 * UU, UU, 0, 0, 0, 0, 1);
    transpose_kernel<<<dim3(UU / 32, UU / 32, 1), tblk>>>(Wr, p_wrT, UU, UU, 0, 0, 0, 0, 1);
    transpose_kernel<<<dim3(UU / 32, UU / 32, 1), tblk>>>(Wo, p_woT, UU, UU, 0, 0, 0, 0, 1);

    // 1. full = tf32(concat(mem, inp));  relr = tf32(relatives)
    {
        size_t total4 = (size_t)BB * KL * UU / 4;
        concat_kernel<<<(unsigned)((total4 + 255) / 256), 256>>>(memories, inputs);
        roundcopy_kernel<<<(unsigned)((total4 + 255) / 256), 256>>>(relatives, p_relr, total4);
    }

    // 2. w_q = inputs @ Wq  (A = rounded inputs inside g_full rows MEM..)
    mma_gemm<128,128,64,32,false><<<dim3(UU/128, QQ/128, BB), 256, SMEM_A>>>(
        p_full + (size_t)MEMN * UU, UU, (long long)KL * UU, 0,
        p_wqT, UU, 0, 0,
        p_wq, UU, (long long)QQ * UU, 0, UU, 1);

    // 3. w_kv = full @ Wkv  [4096 x 2048], rounded output
    mma_gemm<128,128,64,32,true><<<dim3((2*UU)/128, (BB*KL)/128, 1), 256, SMEM_A>>>(
        p_full, UU, 0, 0, p_wkvT, UU, 0, 0, p_wkv, 2*UU, 0, 0, UU, 1);

    // 4. w_r = relatives @ Wr  [4096 x 1024], rounded output
    mma_gemm<128,128,64,32,true><<<dim3(UU/128, (BB*KL)/128, 1), 256, SMEM_A>>>(
        p_relr, UU, 0, 0, p_wrT, UU, 0, 0, p_wr, UU, 0, 0, UU, 1);

    // 5. qc, qr = tf32(wq + biases)
    {
        size_t total4 = (size_t)BB * QQ * UU / 4;
        biasadd_kernel<<<(unsigned)((total4 + 255) / 256), 256>>>(bias_c, bias_r);
    }

    // 6. V^T per head: g_vt[b,h,d,t] = tf32(wkv[b, t, U + h*64 + d])
    transpose_kernel<<<dim3(DHH / 32, KL / 32, BB * HH), tblk>>>(
        p_wkv + UU, p_vt, 2 * UU, KL,
        (long long)KL * 2 * UU, 64,
        (long long)HH * DHH * KL, (long long)DHH * KL, HH);

    // 7. Sc[b,h] = qc(b,h) [Q,64] @ K(b,h)[KL,64]^T
    mma_gemm<128,128,64,32,false><<<dim3(KL/128, QQ/128, BB*HH), 256, SMEM_A>>>(
        p_qc, UU, (long long)QQ * UU, 64,
        p_wkv, 2 * UU, (long long)KL * 2 * UU, 64,
        p_sc, KL, (long long)HH * QQ * KL, (long long)QQ * KL,
        DHH, HH);

    // 8. Sr[b,h] = qr(b,h) @ R(b,h)^T
    mma_gemm<128,128,64,32,false><<<dim3(KL/128, QQ/128, BB*HH), 256, SMEM_A>>>(
        p_qr, UU, (long long)QQ * UU, 64,
        p_wr, UU, (long long)KL * UU, 64,
        p_sr, KL, (long long)HH * QQ * KL, (long long)QQ * KL,
        DHH, HH);

    // 9. masked softmax with relative shift -> P (rounded) in g_sc
    softmax_kernel<<<dim3(QQ, HH, BB), 256>>>();

    // 10. ctx(b,h) = P(b,h) [Q,KL] @ V^T(b,h) [64,KL]^T, rounded output
    mma_gemm<128,64,32,32,true><<<dim3(1, QQ/128, BB*HH), 256, SMEM_B>>>(
        p_sc, KL, (long long)HH * QQ * KL, (long long)QQ * KL,
        p_vt, KL, (long long)HH * DHH * KL, (long long)DHH * KL,
        p_ctx, UU, (long long)QQ * UU, 64,
        KL, HH);

    // 11. out = ctx @ Wo
    mma_gemm<128,128,64,32,false><<<dim3(UU/128, (BB*QQ)/128, 1), 256, SMEM_A>>>(
        p_ctx, UU, 0, 0, p_woT, UU, 0, 0, out, UU, 0, 0, UU, 1);
}